// round 6
// baseline (speedup 1.0000x reference)
#include <cuda_runtime.h>

// Fixed problem shapes
#define BB 16
#define TT 288
#define NN 4096
#define HH 10
#define RR 16
#define TCHUNKS 8
#define TPC (TT / TCHUNKS)        // 36
#define XBLK 8                    // blocks along n in phase A
#define NBLKS (XBLK * BB * TCHUNKS)   // 1024 (co-resident: <= 8/SM * 148 = 1184)
#define K3QC 64                   // phase-B q-chunks (bid & 63)

// Scratch: fully rewritten each replay before reads; counters/flag restored
// to 0 by the tail block each replay -> graph-replay safe.
__device__ float4 g_part[TCHUNKS][BB][NN / 2];  // (s0,c0,s1,c1) per node pair
__device__ float2 g_blk[NBLKS];                 // per-block (sum, cnt)
__device__ float  g_gmean;
__device__ float  g_regp[BB][K3QC][RR];         // regional partial sums
__device__ unsigned int g_ctrA;                 // barrier arrivals
__device__ unsigned int g_ctrC;                 // tail arrivals
__device__ volatile unsigned int g_flag;        // gmean-ready flag

// ---------------------------------------------------------------------------
// Single fused kernel. 1024 blocks x 256 threads, all co-resident.
//   Phase A : streaming pass over 151MB -> per-(tc,b,q) partials + block (s,c)
//   Barrier : last arriver reduces 1024 partials -> gmean, sets flag
//   Phase B : combine tc-slices per node -> pred_speed + regional partials
//   Tail    : last-done block -> regional output + reset counters
// ---------------------------------------------------------------------------
__global__ void __launch_bounds__(256, 8)
fused_all(const float4* __restrict__ data, const int* __restrict__ cid,
          float* __restrict__ out) {
    const int tid = threadIdx.x;
    const int bid = blockIdx.x;
    const int lane = tid & 31;
    const int wid  = tid >> 5;

    // ===================== Phase A: heavy streaming pass =====================
    {
        const int x  = bid & 7;
        const int b  = (bid >> 3) & 15;
        const int tc = bid >> 7;
        const int q  = x * 256 + tid;

        const float4* __restrict__ p =
            data + (size_t)(b * TT + tc * TPC) * (NN / 2) + q;

        float s0 = 0.f, s1 = 0.f, c0 = 0.f, c1 = 0.f;
        #pragma unroll 6
        for (int t = 0; t < TPC; ++t) {
            float4 v = __ldcs(p);
            p += NN / 2;
            if (v.x != -1.0f) { s0 += v.x; c0 += 1.0f; }
            if (v.z != -1.0f) { s1 += v.z; c1 += 1.0f; }
        }
        g_part[tc][b][q] = make_float4(s0, c0, s1, c1);

        float s = s0 + s1;
        float c = c0 + c1;
        #pragma unroll
        for (int o = 16; o > 0; o >>= 1) {
            s += __shfl_down_sync(0xffffffffu, s, o);
            c += __shfl_down_sync(0xffffffffu, c, o);
        }
        __shared__ float sh_s[8], sh_c[8];
        if (lane == 0) { sh_s[wid] = s; sh_c[wid] = c; }
        __syncthreads();
        if (tid == 0) {
            s = 0.f; c = 0.f;
            #pragma unroll
            for (int w = 0; w < 8; ++w) { s += sh_s[w]; c += sh_c[w]; }
            g_blk[bid] = make_float2(s, c);
        }
    }

    // ===================== Grid barrier + gmean ==============================
    {
        __shared__ bool amLastA;
        __syncthreads();               // all block stores issued
        if (tid == 0) {
            __threadfence();           // publish g_part / g_blk
            amLastA = (atomicAdd(&g_ctrA, 1u) == NBLKS - 1);
        }
        __syncthreads();

        if (amLastA) {
            // 256 threads reduce 1024 float2 (L2-hot)
            float s = 0.f, c = 0.f;
            #pragma unroll
            for (int i = tid; i < NBLKS; i += 256) {
                float2 v = g_blk[i];
                s += v.x; c += v.y;
            }
            #pragma unroll
            for (int o = 16; o > 0; o >>= 1) {
                s += __shfl_down_sync(0xffffffffu, s, o);
                c += __shfl_down_sync(0xffffffffu, c, o);
            }
            __shared__ float rs_s[8], rs_c[8];
            if (lane == 0) { rs_s[wid] = s; rs_c[wid] = c; }
            __syncthreads();
            if (tid == 0) {
                s = 0.f; c = 0.f;
                #pragma unroll
                for (int w = 0; w < 8; ++w) { s += rs_s[w]; c += rs_c[w]; }
                g_gmean = s / fmaxf(c, 1.0f);
                __threadfence();
                g_flag = 1u;           // release
            }
        }

        if (tid == 0) {
            while (g_flag == 0u) __nanosleep(64);
        }
        __syncthreads();
        __threadfence();               // acquire: g_gmean + peers' g_part
    }

    // ===================== Phase B: outputs ==================================
    const float gm = g_gmean;
    {
        const int chunk = bid & 63;        // 0..63
        const int b     = bid >> 6;        // 0..15
        const int ql    = lane & 3;
        const int tc    = lane >> 2;       // 0..7
        const int q     = chunk * 32 + wid * 4 + ql;   // node-pair index

        __shared__ float rs[RR];
        if (tid < RR) rs[tid] = 0.f;
        __syncthreads();

        float4 v = g_part[tc][b][q];
        float s0 = v.x, c0 = v.y, s1 = v.z, c1 = v.w;
        #pragma unroll
        for (int m = 4; m <= 16; m <<= 1) {
            s0 += __shfl_xor_sync(0xffffffffu, s0, m);
            c0 += __shfl_xor_sync(0xffffffffu, c0, m);
            s1 += __shfl_xor_sync(0xffffffffu, s1, m);
            c1 += __shfl_xor_sync(0xffffffffu, c1, m);
        }

        const float invT = 1.0f / (float)TT;
        const float m0 = (s0 + ((float)TT - c0) * gm) * invT;
        const float m1 = (s1 + ((float)TT - c1) * gm) * invT;
        const float2 mm = make_float2(m0, m1);

        float2* __restrict__ o2 = (float2*)out;
        o2[((size_t)b * HH + tc) * (NN / 2) + q] = mm;
        if (tc < 2)
            o2[((size_t)b * HH + tc + 8) * (NN / 2) + q] = mm;

        if (tc == 0) {
            const int2 cc = ((const int2*)cid)[q];
            atomicAdd(&rs[cc.x], m0);
            atomicAdd(&rs[cc.y], m1);
        }
        __syncthreads();
        if (tid < RR)
            g_regp[b][chunk][tid] = rs[tid];
    }

    // ===================== Tail: regional output + reset =====================
    {
        __shared__ bool amLastC;
        __syncthreads();
        if (tid == 0) {
            __threadfence();
            amLastC = (atomicAdd(&g_ctrC, 1u) == NBLKS - 1);
        }
        __syncthreads();
        if (!amLastC) return;

        __shared__ float rcnt[RR];
        if (tid < RR) rcnt[tid] = 0.f;
        __syncthreads();
        for (int i = tid; i < NN; i += 256)
            atomicAdd(&rcnt[cid[i]], 1.0f);
        __syncthreads();

        const int bb = tid >> 4;
        const int r  = tid & 15;
        float acc = 0.f;
        #pragma unroll
        for (int x = 0; x < K3QC; ++x)
            acc += g_regp[bb][x][r];
        const float val = acc / fmaxf(rcnt[r], 1.0f);

        float* __restrict__ ro = out + (size_t)BB * HH * NN;
        #pragma unroll
        for (int h = 0; h < HH; ++h)
            ro[((size_t)bb * HH + h) * RR + r] = val;

        if (tid == 0) {                // restore for next graph replay
            g_ctrA = 0;
            g_ctrC = 0;
            g_flag = 0;
        }
    }
}

// ---------------------------------------------------------------------------
extern "C" void kernel_launch(void* const* d_in, const int* in_sizes, int n_in,
                              void* d_out, int out_size) {
    const float4* data = (const float4*)d_in[0];
    const int*    cid  = (const int*)d_in[1];
    float*        out  = (float*)d_out;

    fused_all<<<NBLKS, 256>>>(data, cid, out);
}

// round 7
// speedup vs baseline: 1.0384x; 1.0384x over previous
#include <cuda_runtime.h>

// Fixed problem shapes
#define BB 16
#define TT 288
#define NN 4096
#define HH 10
#define RR 16
#define TCHUNKS 9
#define TPC (TT / TCHUNKS)            // 32
#define XBLK 8                        // k1 blocks along n
#define NBLKS1 (XBLK * BB * TCHUNKS)  // 1152
#define K2QC 64                       // epilogue q-chunks (32 q-pairs each)
#define NBLKS2 (K2QC * BB)            // 1024

// Scratch: fully rewritten each replay before reads; counter restored to 0.
__device__ float4 g_part[TCHUNKS][BB][NN / 2];  // (s0,c0,s1,c1) per node pair
__device__ float2 g_blk[NBLKS1];                // per-k1-block (sum, cnt)
__device__ float  g_regp[BB][K2QC][RR];         // regional partial sums
__device__ unsigned int g_ctr;                  // zero at load; restored each replay

// ---------------------------------------------------------------------------
// Kernel 1: heavy streaming pass over 151MB. R4's exact recipe:
// grid (8,16,9) = 1152 blocks x 256 thr, TPC=32, unroll 8 (deep LDG batching).
// ---------------------------------------------------------------------------
__global__ void __launch_bounds__(256) k1_main(const float4* __restrict__ data) {
    const int tid = threadIdx.x;
    const int b   = blockIdx.y;
    const int tc  = blockIdx.z;
    const int q   = blockIdx.x * 256 + tid;   // float4 column in [0, NN/2)

    const float4* __restrict__ p =
        data + (size_t)(b * TT + tc * TPC) * (NN / 2) + q;

    float s0 = 0.f, s1 = 0.f, c0 = 0.f, c1 = 0.f;
    #pragma unroll 8
    for (int t = 0; t < TPC; ++t) {
        float4 v = __ldcs(p);
        p += NN / 2;
        if (v.x != -1.0f) { s0 += v.x; c0 += 1.0f; }
        if (v.z != -1.0f) { s1 += v.z; c1 += 1.0f; }
    }
    g_part[tc][b][q] = make_float4(s0, c0, s1, c1);

    // Block-reduce (sum, cnt) -> g_blk
    float s = s0 + s1;
    float c = c0 + c1;
    #pragma unroll
    for (int o = 16; o > 0; o >>= 1) {
        s += __shfl_down_sync(0xffffffffu, s, o);
        c += __shfl_down_sync(0xffffffffu, c, o);
    }
    __shared__ float sh_s[8], sh_c[8];
    const int wid = tid >> 5, lane = tid & 31;
    if (lane == 0) { sh_s[wid] = s; sh_c[wid] = c; }
    __syncthreads();
    if (tid == 0) {
        s = 0.f; c = 0.f;
        #pragma unroll
        for (int w = 0; w < 8; ++w) { s += sh_s[w]; c += sh_c[w]; }
        const int bid = (blockIdx.z * BB + blockIdx.y) * XBLK + blockIdx.x;
        g_blk[bid] = make_float2(s, c);
    }
}

// ---------------------------------------------------------------------------
// Kernel 2 (epilogue): 1024 blocks x 256 thr.
//  (a) every block redundantly reduces g_blk (9KB, L2-hot) -> gmean
//  (b) 8 threads per node-pair combine tc-slices via shuffles (tc==0 lane
//      also folds slice 8) -> imputed mean
//  (c) float2 pred_speed stores tiled over H=10
//  (d) regional partials via shared atomics; last-block tail writes regional
// ---------------------------------------------------------------------------
__global__ void __launch_bounds__(256) k2_epilogue(const int* __restrict__ cid,
                                                   float* __restrict__ out) {
    const int tid  = threadIdx.x;
    const int lane = tid & 31;
    const int wid  = tid >> 5;

    // ---- (a) redundant gmean: 1152 float2, 4-5 per thread, one block reduce
    float s = 0.f, c = 0.f;
    for (int i = tid; i < NBLKS1; i += 256) {
        float2 v = g_blk[i];
        s += v.x; c += v.y;
    }
    #pragma unroll
    for (int o = 16; o > 0; o >>= 1) {
        s += __shfl_down_sync(0xffffffffu, s, o);
        c += __shfl_down_sync(0xffffffffu, c, o);
    }
    __shared__ float sh_s[8], sh_c[8];
    __shared__ float sh_gm;
    if (lane == 0) { sh_s[wid] = s; sh_c[wid] = c; }

    __shared__ float rs[RR];
    if (tid < RR) rs[tid] = 0.f;
    __syncthreads();
    if (tid == 0) {
        s = 0.f; c = 0.f;
        #pragma unroll
        for (int w = 0; w < 8; ++w) { s += sh_s[w]; c += sh_c[w]; }
        sh_gm = s / fmaxf(c, 1.0f);
    }
    __syncthreads();
    const float gm = sh_gm;

    // ---- (b) combine tc slices: 8 threads per node-pair
    const int chunk = blockIdx.x & 63;       // 0..63
    const int b     = blockIdx.x >> 6;       // 0..15
    const int ql    = lane & 3;
    const int tc    = lane >> 2;             // 0..7
    const int q     = chunk * 32 + wid * 4 + ql;   // node-pair index

    float4 v = g_part[tc][b][q];
    float s0 = v.x, c0 = v.y, s1 = v.z, c1 = v.w;
    if (tc == 0) {                            // fold 9th slice
        float4 v8 = g_part[8][b][q];
        s0 += v8.x; c0 += v8.y; s1 += v8.z; c1 += v8.w;
    }
    #pragma unroll
    for (int m = 4; m <= 16; m <<= 1) {
        s0 += __shfl_xor_sync(0xffffffffu, s0, m);
        c0 += __shfl_xor_sync(0xffffffffu, c0, m);
        s1 += __shfl_xor_sync(0xffffffffu, s1, m);
        c1 += __shfl_xor_sync(0xffffffffu, c1, m);
    }

    const float invT = 1.0f / (float)TT;
    const float m0 = (s0 + ((float)TT - c0) * gm) * invT;
    const float m1 = (s1 + ((float)TT - c1) * gm) * invT;
    const float2 mm = make_float2(m0, m1);

    // ---- (c) pred_speed stores: h = tc, plus h = tc+8 for tc<2
    float2* __restrict__ o2 = (float2*)out;
    o2[((size_t)b * HH + tc) * (NN / 2) + q] = mm;
    if (tc < 2)
        o2[((size_t)b * HH + tc + 8) * (NN / 2) + q] = mm;

    // ---- (d) regional partials
    if (tc == 0) {
        const int2 cc = ((const int2*)cid)[q];
        atomicAdd(&rs[cc.x], m0);
        atomicAdd(&rs[cc.y], m1);
    }
    __syncthreads();
    if (tid < RR)
        g_regp[b][chunk][tid] = rs[tid];

    // ---- last-block-done: regional output + counter reset
    __shared__ bool amLast;
    __syncthreads();
    if (tid == 0) {
        __threadfence();
        amLast = (atomicAdd(&g_ctr, 1u) == NBLKS2 - 1);
    }
    __syncthreads();
    if (!amLast) return;

    __shared__ float rcnt[RR];
    if (tid < RR) rcnt[tid] = 0.f;
    __syncthreads();
    for (int i = tid; i < NN; i += 256)
        atomicAdd(&rcnt[cid[i]], 1.0f);
    __syncthreads();

    const int bb = tid >> 4;
    const int r  = tid & 15;
    float acc = 0.f;
    #pragma unroll
    for (int x = 0; x < K2QC; ++x)
        acc += g_regp[bb][x][r];
    const float val = acc / fmaxf(rcnt[r], 1.0f);

    float* __restrict__ ro = out + (size_t)BB * HH * NN;
    #pragma unroll
    for (int h = 0; h < HH; ++h)
        ro[((size_t)bb * HH + h) * RR + r] = val;

    if (tid == 0) g_ctr = 0;   // restore for next graph replay
}

// ---------------------------------------------------------------------------
extern "C" void kernel_launch(void* const* d_in, const int* in_sizes, int n_in,
                              void* d_out, int out_size) {
    const float4* data = (const float4*)d_in[0];
    const int*    cid  = (const int*)d_in[1];
    float*        out  = (float*)d_out;

    dim3 g1(XBLK, BB, TCHUNKS);   // (8,16,9) = 1152 blocks
    k1_main<<<g1, 256>>>(data);
    k2_epilogue<<<NBLKS2, 256>>>(cid, out);
}